// round 1
// baseline (speedup 1.0000x reference)
#include <cuda_runtime.h>
#include <cstdint>

#define NDRUG 100000
#define NPROT 100000
#define DIM   128

// -------- scratch (no runtime allocation allowed) --------
__device__ float g_hd1[(size_t)NDRUG * DIM];
__device__ float g_hp1[(size_t)NPROT * DIM];
__device__ float g_hd2[(size_t)NDRUG * DIM];
__device__ float g_hp2[(size_t)NPROT * DIM];
__device__ float g_agg1[(size_t)NDRUG * DIM];   // DDI aggregate (drug dst)
__device__ float g_agg2[(size_t)NDRUG * DIM];   // PDI aggregate (drug dst)
__device__ float g_aggp[(size_t)NPROT * DIM];   // PPI aggregate (protein dst)
// 6 rsqrt-degree arrays, each NDRUG (=NPROT) long:
// [0]=ddi_out [1]=ddi_in [2]=pdi_out [3]=pdi_in [4]=ppi_out [5]=ppi_in
__device__ float g_rs[(size_t)6 * NDRUG];

// -------- degree kernels --------
__global__ void count_kernel(const int* __restrict__ idx, float* __restrict__ cnt, int n) {
    int i = blockIdx.x * blockDim.x + threadIdx.x;
    if (i < n) atomicAdd(&cnt[idx[i]], 1.0f);
}

__global__ void rsqrt_kernel(float* __restrict__ p, int n) {
    int i = blockIdx.x * blockDim.x + threadIdx.x;
    if (i < n) p[i] = rsqrtf(fmaxf(p[i], 1.0f));
}

// -------- edge scatter: agg[dst] += h[src] * rs_out[src] --------
// One warp per edge; each lane handles 4 floats via a single red.global.add.v4.f32.
__global__ void scatter_kernel(const float* __restrict__ h,
                               const int* __restrict__ src,
                               const int* __restrict__ dst,
                               const float* __restrict__ rs,
                               float* __restrict__ agg, int nE) {
    int t = blockIdx.x * blockDim.x + threadIdx.x;
    int e = t >> 5;
    int lane = t & 31;
    if (e >= nE) return;
    int s = __ldg(src + e);
    int d = __ldg(dst + e);
    float sc = __ldg(rs + s);
    float4 v = __ldg(reinterpret_cast<const float4*>(h + (size_t)s * DIM) + lane);
    v.x *= sc; v.y *= sc; v.z *= sc; v.w *= sc;
    float* ap = agg + (size_t)d * DIM + lane * 4;
    asm volatile("red.global.add.v4.f32 [%0], {%1,%2,%3,%4};"
                 :: "l"(ap), "f"(v.x), "f"(v.y), "f"(v.z), "f"(v.w)
                 : "memory");
}

// -------- fused GEMM epilogue stage --------
// out[i,:] = act( rs1[i]*A1[i,:] @ W1  (+ rs2[i]*A2[i,:] @ W2)  + b1 (+ b2) )
// Block: 256 threads computes a 64-row x 128-col tile. Each thread: 8 rows x 4 cols.
template<bool RELU, bool TWO>
__global__ void __launch_bounds__(256)
gemm_kernel(const float* __restrict__ A1, const float* __restrict__ rs1,
            const float* __restrict__ A2, const float* __restrict__ rs2,
            const float* __restrict__ W1, const float* __restrict__ W2,
            const float* __restrict__ b1, const float* __restrict__ b2,
            float* __restrict__ out, int nrows) {
    __shared__ float As[32][65];    // [k][row] transposed A tile (pad 65: conflict-free)
    __shared__ float Ws[32][132];   // [k][col] W tile (row stride 528B, 16B aligned)

    const int t = threadIdx.x;
    const int c = t & 31;     // column group: cols 4c..4c+3
    const int r = t >> 5;     // row group (warp id): rows r*8..r*8+7
    const int row0 = blockIdx.x * 64;

    float acc[8][4];
#pragma unroll
    for (int i = 0; i < 8; i++)
#pragma unroll
        for (int j = 0; j < 4; j++) acc[i][j] = 0.0f;

    const int nsrc = TWO ? 2 : 1;
    for (int s = 0; s < nsrc; s++) {
        const float* A  = s ? A2  : A1;
        const float* rs = s ? rs2 : rs1;
        const float* W  = s ? W2  : W1;
        for (int kc = 0; kc < DIM; kc += 32) {
            // Load A tile (64x32), folding in the dst-degree scale.
#pragma unroll
            for (int i = 0; i < 8; i++) {
                int e  = t + 256 * i;
                int rr = e >> 5;
                int kk = e & 31;
                int row = row0 + rr;
                float v = 0.0f;
                if (row < nrows) v = A[(size_t)row * DIM + kc + kk] * __ldg(rs + row);
                As[kk][rr] = v;
            }
            // Load W tile (32x128) as float4s.
#pragma unroll
            for (int i = 0; i < 4; i++) {
                int f  = t + 256 * i;          // float4 index, 32 per k-row
                int kk = f >> 5;
                int jj = (f & 31) * 4;
                float4 w4 = __ldg(reinterpret_cast<const float4*>(
                    W + (size_t)(kc + kk) * DIM + jj));
                *reinterpret_cast<float4*>(&Ws[kk][jj]) = w4;
            }
            __syncthreads();
#pragma unroll
            for (int k = 0; k < 32; k++) {
                float4 w = *reinterpret_cast<const float4*>(&Ws[k][c * 4]);
                float a[8];
#pragma unroll
                for (int i = 0; i < 8; i++) a[i] = As[k][r * 8 + i];  // broadcast reads
#pragma unroll
                for (int i = 0; i < 8; i++) {
                    acc[i][0] += a[i] * w.x;
                    acc[i][1] += a[i] * w.y;
                    acc[i][2] += a[i] * w.z;
                    acc[i][3] += a[i] * w.w;
                }
            }
            __syncthreads();
        }
    }

    // Epilogue: bias (+bias2), optional ReLU, vectorized store.
    float4 bb;
    bb.x = __ldg(b1 + c * 4 + 0);
    bb.y = __ldg(b1 + c * 4 + 1);
    bb.z = __ldg(b1 + c * 4 + 2);
    bb.w = __ldg(b1 + c * 4 + 3);
    if (TWO) {
        bb.x += __ldg(b2 + c * 4 + 0);
        bb.y += __ldg(b2 + c * 4 + 1);
        bb.z += __ldg(b2 + c * 4 + 2);
        bb.w += __ldg(b2 + c * 4 + 3);
    }
#pragma unroll
    for (int i = 0; i < 8; i++) {
        int row = row0 + r * 8 + i;
        if (row < nrows) {
            float4 o;
            o.x = acc[i][0] + bb.x;
            o.y = acc[i][1] + bb.y;
            o.z = acc[i][2] + bb.z;
            o.w = acc[i][3] + bb.w;
            if (RELU) {
                o.x = fmaxf(o.x, 0.0f);
                o.y = fmaxf(o.y, 0.0f);
                o.z = fmaxf(o.z, 0.0f);
                o.w = fmaxf(o.w, 0.0f);
            }
            *reinterpret_cast<float4*>(out + (size_t)row * DIM + c * 4) = o;
        }
    }
}

// -------- host orchestration --------
static void run_layer(const float* hd_in, const float* hp_in,
                      float* hd_out, float* hp_out,
                      const float* W, const float* b, bool relu,
                      const int* ddi_s, const int* ddi_d, int nE_ddi,
                      const int* pdi_s, const int* pdi_d, int nE_pdi,
                      const int* ppi_s, const int* ppi_d, int nE_ppi,
                      float* agg1, float* agg2, float* aggp, float* rs) {
    const size_t fbytes = (size_t)NDRUG * DIM * sizeof(float);
    cudaMemsetAsync(agg1, 0, fbytes, 0);
    cudaMemsetAsync(agg2, 0, fbytes, 0);
    cudaMemsetAsync(aggp, 0, (size_t)NPROT * DIM * sizeof(float), 0);

    // scatter: one warp per edge -> 8 edges per 256-thread block
    scatter_kernel<<<(nE_ddi + 7) / 8, 256>>>(hd_in, ddi_s, ddi_d, rs + 0 * NDRUG, agg1, nE_ddi);
    scatter_kernel<<<(nE_pdi + 7) / 8, 256>>>(hp_in, pdi_s, pdi_d, rs + 2 * NDRUG, agg2, nE_pdi);
    scatter_kernel<<<(nE_ppi + 7) / 8, 256>>>(hp_in, ppi_s, ppi_d, rs + 4 * NDRUG, aggp, nE_ppi);

    const int gblocks = (NDRUG + 63) / 64;
    // drug dst: d_ddi + d_pdi  (relations 0 and 1)
    if (relu)
        gemm_kernel<true, true><<<gblocks, 256>>>(
            agg1, rs + 1 * NDRUG, agg2, rs + 3 * NDRUG,
            W + 0 * DIM * DIM, W + 1 * DIM * DIM, b + 0 * DIM, b + 1 * DIM,
            hd_out, NDRUG);
    else
        gemm_kernel<false, true><<<gblocks, 256>>>(
            agg1, rs + 1 * NDRUG, agg2, rs + 3 * NDRUG,
            W + 0 * DIM * DIM, W + 1 * DIM * DIM, b + 0 * DIM, b + 1 * DIM,
            hd_out, NDRUG);
    // protein dst: p_ppi (relation 2)
    if (relu)
        gemm_kernel<true, false><<<gblocks, 256>>>(
            aggp, rs + 5 * NDRUG, nullptr, nullptr,
            W + 2 * DIM * DIM, nullptr, b + 2 * DIM, nullptr,
            hp_out, NPROT);
    else
        gemm_kernel<false, false><<<gblocks, 256>>>(
            aggp, rs + 5 * NDRUG, nullptr, nullptr,
            W + 2 * DIM * DIM, nullptr, b + 2 * DIM, nullptr,
            hp_out, NPROT);
}

extern "C" void kernel_launch(void* const* d_in, const int* in_sizes, int n_in,
                              void* d_out, int out_size) {
    const float* hd0   = (const float*)d_in[0];
    const float* hp0   = (const float*)d_in[1];
    const int*   ddi_s = (const int*)d_in[2];
    const int*   ddi_d = (const int*)d_in[3];
    const int*   pdi_s = (const int*)d_in[4];
    const int*   pdi_d = (const int*)d_in[5];
    const int*   ppi_s = (const int*)d_in[6];
    const int*   ppi_d = (const int*)d_in[7];
    const float* W1 = (const float*)d_in[8];
    const float* b1 = (const float*)d_in[9];
    const float* W2 = (const float*)d_in[10];
    const float* b2 = (const float*)d_in[11];
    const float* W3 = (const float*)d_in[12];
    const float* b3 = (const float*)d_in[13];

    const int nE_ddi = in_sizes[2];
    const int nE_pdi = in_sizes[4];
    const int nE_ppi = in_sizes[6];

    float *hd1, *hp1, *hd2, *hp2, *agg1, *agg2, *aggp, *rs;
    cudaGetSymbolAddress((void**)&hd1, g_hd1);
    cudaGetSymbolAddress((void**)&hp1, g_hp1);
    cudaGetSymbolAddress((void**)&hd2, g_hd2);
    cudaGetSymbolAddress((void**)&hp2, g_hp2);
    cudaGetSymbolAddress((void**)&agg1, g_agg1);
    cudaGetSymbolAddress((void**)&agg2, g_agg2);
    cudaGetSymbolAddress((void**)&aggp, g_aggp);
    cudaGetSymbolAddress((void**)&rs, g_rs);

    // ---- degrees (recomputed every call; edges are inputs) ----
    cudaMemsetAsync(rs, 0, (size_t)6 * NDRUG * sizeof(float), 0);
    {
        int cb = (nE_ddi + 255) / 256;
        count_kernel<<<cb, 256>>>(ddi_s, rs + 0 * NDRUG, nE_ddi);
        count_kernel<<<cb, 256>>>(ddi_d, rs + 1 * NDRUG, nE_ddi);
        cb = (nE_pdi + 255) / 256;
        count_kernel<<<cb, 256>>>(pdi_s, rs + 2 * NDRUG, nE_pdi);
        count_kernel<<<cb, 256>>>(pdi_d, rs + 3 * NDRUG, nE_pdi);
        cb = (nE_ppi + 255) / 256;
        count_kernel<<<cb, 256>>>(ppi_s, rs + 4 * NDRUG, nE_ppi);
        count_kernel<<<cb, 256>>>(ppi_d, rs + 5 * NDRUG, nE_ppi);
        rsqrt_kernel<<<(6 * NDRUG + 255) / 256, 256>>>(rs, 6 * NDRUG);
    }

    float* outd = (float*)d_out;
    float* outp = outd + (size_t)NDRUG * DIM;

    // layer 1: inputs -> (hd1, hp1), ReLU
    run_layer(hd0, hp0, hd1, hp1, W1, b1, true,
              ddi_s, ddi_d, nE_ddi, pdi_s, pdi_d, nE_pdi, ppi_s, ppi_d, nE_ppi,
              agg1, agg2, aggp, rs);
    // layer 2: (hd1, hp1) -> (hd2, hp2), ReLU
    run_layer(hd1, hp1, hd2, hp2, W2, b2, true,
              ddi_s, ddi_d, nE_ddi, pdi_s, pdi_d, nE_pdi, ppi_s, ppi_d, nE_ppi,
              agg1, agg2, aggp, rs);
    // layer 3: (hd2, hp2) -> d_out, no activation
    run_layer(hd2, hp2, outd, outp, W3, b3, false,
              ddi_s, ddi_d, nE_ddi, pdi_s, pdi_d, nE_pdi, ppi_s, ppi_d, nE_ppi,
              agg1, agg2, aggp, rs);
}

// round 3
// speedup vs baseline: 1.3688x; 1.3688x over previous
#include <cuda_runtime.h>
#include <cstdint>

#define NDRUG 100000
#define NPROT 100000
#define DIM   128
#define SA    132   // smem row stride in floats (conflict-free for quad patterns)

// ---------------- scratch (no runtime allocation allowed) ----------------
__device__ float g_hd1[(size_t)NDRUG * DIM];
__device__ float g_hp1[(size_t)NPROT * DIM];
__device__ float g_hd2[(size_t)NDRUG * DIM];
__device__ float g_hp2[(size_t)NPROT * DIM];
__device__ float g_agg1[(size_t)NDRUG * DIM];   // DDI aggregate (drug dst)
__device__ float g_agg2[(size_t)NDRUG * DIM];   // PDI aggregate (drug dst)
__device__ float g_aggp[(size_t)NPROT * DIM];   // PPI aggregate (protein dst)
// 6 rsqrt-degree arrays: [0]=ddi_out [1]=ddi_in [2]=pdi_out [3]=pdi_in [4]=ppi_out [5]=ppi_in
__device__ float g_rs[(size_t)6 * NDRUG];
// transposed + tf32-rounded weights: 9 matrices of [n][k]
__device__ float g_Wt[(size_t)9 * DIM * DIM];

// ---------------- degree kernels ----------------
__global__ void count_kernel(const int* __restrict__ idx, float* __restrict__ cnt, int n) {
    int i = blockIdx.x * blockDim.x + threadIdx.x;
    if (i < n) atomicAdd(&cnt[idx[i]], 1.0f);
}
__global__ void rsqrt_kernel(float* __restrict__ p, int n) {
    int i = blockIdx.x * blockDim.x + threadIdx.x;
    if (i < n) p[i] = rsqrtf(fmaxf(p[i], 1.0f));
}
// transpose 3 stacked [128x128] weight matrices to [n][k], rounding to tf32 once
__global__ void transpose_w(const float* __restrict__ W, float* __restrict__ Wt) {
    int i = blockIdx.x * blockDim.x + threadIdx.x;
    if (i < 3 * DIM * DIM) {
        int rel = i >> 14, rem = i & 16383;
        int k = rem >> 7, n = rem & 127;
        float v = W[i];
        uint32_t u;
        asm("cvt.rna.tf32.f32 %0, %1;" : "=r"(u) : "f"(v));
        Wt[(rel << 14) + (n << 7) + k] = __uint_as_float(u);
    }
}

// ---------------- edge scatter: agg[dst] += h[src] * rs_out[src] ----------------
__global__ void scatter_kernel(const float* __restrict__ h,
                               const int* __restrict__ src,
                               const int* __restrict__ dst,
                               const float* __restrict__ rs,
                               float* __restrict__ agg, int nE) {
    int t = blockIdx.x * blockDim.x + threadIdx.x;
    int e = t >> 5;
    int lane = t & 31;
    if (e >= nE) return;
    int s = __ldg(src + e);
    int d = __ldg(dst + e);
    float sc = __ldg(rs + s);
    float4 v = __ldg(reinterpret_cast<const float4*>(h + (size_t)s * DIM) + lane);
    v.x *= sc; v.y *= sc; v.z *= sc; v.w *= sc;
    float* ap = agg + (size_t)d * DIM + lane * 4;
    asm volatile("red.global.add.v4.f32 [%0], {%1,%2,%3,%4};"
                 :: "l"(ap), "f"(v.x), "f"(v.y), "f"(v.z), "f"(v.w) : "memory");
}

// ---------------- tf32 mma.sync GEMM ----------------
// out[m,:] = act( rs1[m]*A1[m,:] @ W1 (+ rs2[m]*A2[m,:] @ W2) + b1 (+ b2) )
// CTA = 128x128 tile, full K=128 in smem. 8 warps (2m x 4n), warp tile 64x32.
__device__ __forceinline__ void mma_tf32(float c[4], const uint32_t a[4], const uint32_t b[2]) {
    asm volatile(
        "mma.sync.aligned.m16n8k8.row.col.f32.tf32.tf32.f32 "
        "{%0,%1,%2,%3}, {%4,%5,%6,%7}, {%8,%9}, {%0,%1,%2,%3};"
        : "+f"(c[0]), "+f"(c[1]), "+f"(c[2]), "+f"(c[3])
        : "r"(a[0]), "r"(a[1]), "r"(a[2]), "r"(a[3]), "r"(b[0]), "r"(b[1]));
}

template<bool RELU, bool TWO>
__global__ void __launch_bounds__(256)
gemm_mma(const float* __restrict__ A1, const float* __restrict__ rs1,
         const float* __restrict__ A2, const float* __restrict__ rs2,
         const float* __restrict__ Wt1, const float* __restrict__ Wt2,
         const float* __restrict__ b1, const float* __restrict__ b2,
         float* __restrict__ out, int nrows) {
    extern __shared__ float sm[];
    float* As = sm;               // [128][SA]
    float* Ws = sm + 128 * SA;    // [128][SA]

    const int t = threadIdx.x;
    const int lane = t & 31, wid = t >> 5;
    const int wm = wid >> 2, wn = wid & 3;      // 2 x 4 warp grid
    const int row0 = blockIdx.x * 128;
    const int qid = lane >> 2, qtl = lane & 3;  // quad id / thread-in-quad

    float acc[4][4][4];
#pragma unroll
    for (int mi = 0; mi < 4; mi++)
#pragma unroll
        for (int ni = 0; ni < 4; ni++)
#pragma unroll
            for (int j = 0; j < 4; j++) acc[mi][ni][j] = 0.0f;

    const int nsrc = TWO ? 2 : 1;
    for (int s = 0; s < nsrc; s++) {
        const float* A  = s ? A2  : A1;
        const float* rs = s ? rs2 : rs1;
        const float* Wt = s ? Wt2 : Wt1;
        if (s) __syncthreads();   // prior mma reads done before smem overwrite

        // A tile: scale by dst-degree rsqrt, round to tf32, zero-pad past nrows
#pragma unroll
        for (int i = 0; i < 16; i++) {
            int e = t + 256 * i;
            int r = e >> 5, c4 = e & 31;
            int row = row0 + r;
            float4 v = make_float4(0.f, 0.f, 0.f, 0.f);
            if (row < nrows) {
                v = __ldg(reinterpret_cast<const float4*>(A + (size_t)row * DIM) + c4);
                float sc = __ldg(rs + row);
                v.x *= sc; v.y *= sc; v.z *= sc; v.w *= sc;
            }
            uint4 u;
            asm("cvt.rna.tf32.f32 %0, %1;" : "=r"(u.x) : "f"(v.x));
            asm("cvt.rna.tf32.f32 %0, %1;" : "=r"(u.y) : "f"(v.y));
            asm("cvt.rna.tf32.f32 %0, %1;" : "=r"(u.z) : "f"(v.z));
            asm("cvt.rna.tf32.f32 %0, %1;" : "=r"(u.w) : "f"(v.w));
            *reinterpret_cast<uint4*>(&As[r * SA + c4 * 4]) = u;
        }
        // W tile [n][k] (already tf32-rounded)
#pragma unroll
        for (int i = 0; i < 16; i++) {
            int e = t + 256 * i;
            int r = e >> 5, c4 = e & 31;
            float4 v = __ldg(reinterpret_cast<const float4*>(Wt + (size_t)r * DIM) + c4);
            *reinterpret_cast<float4*>(&Ws[r * SA + c4 * 4]) = v;
        }
        __syncthreads();

        // 16 k-steps of m16n8k8
#pragma unroll
        for (int ks = 0; ks < 16; ks++) {
            const int k0 = ks * 8;
            uint32_t a[4][4];
#pragma unroll
            for (int mi = 0; mi < 4; mi++) {
                const float* p = &As[(wm * 64 + mi * 16 + qid) * SA + k0 + qtl];
                a[mi][0] = __float_as_uint(p[0]);
                a[mi][1] = __float_as_uint(p[8 * SA]);
                a[mi][2] = __float_as_uint(p[4]);
                a[mi][3] = __float_as_uint(p[8 * SA + 4]);
            }
            uint32_t b[4][2];
#pragma unroll
            for (int ni = 0; ni < 4; ni++) {
                const float* p = &Ws[(wn * 32 + ni * 8 + qid) * SA + k0 + qtl];
                b[ni][0] = __float_as_uint(p[0]);
                b[ni][1] = __float_as_uint(p[4]);
            }
#pragma unroll
            for (int mi = 0; mi < 4; mi++)
#pragma unroll
                for (int ni = 0; ni < 4; ni++)
                    mma_tf32(acc[mi][ni], a[mi], b[ni]);
        }
    }

    // Epilogue: bias (+bias2), optional ReLU, float2 stores
#pragma unroll
    for (int ni = 0; ni < 4; ni++) {
        int col = wn * 32 + ni * 8 + qtl * 2;
        float bb0 = __ldg(b1 + col)     + (TWO ? __ldg(b2 + col)     : 0.0f);
        float bb1 = __ldg(b1 + col + 1) + (TWO ? __ldg(b2 + col + 1) : 0.0f);
#pragma unroll
        for (int mi = 0; mi < 4; mi++) {
            int r0 = row0 + wm * 64 + mi * 16 + qid;
            if (r0 < nrows) {
                float2 o;
                o.x = acc[mi][ni][0] + bb0;
                o.y = acc[mi][ni][1] + bb1;
                if (RELU) { o.x = fmaxf(o.x, 0.0f); o.y = fmaxf(o.y, 0.0f); }
                *reinterpret_cast<float2*>(out + (size_t)r0 * DIM + col) = o;
            }
            int r1 = r0 + 8;
            if (r1 < nrows) {
                float2 o;
                o.x = acc[mi][ni][2] + bb0;
                o.y = acc[mi][ni][3] + bb1;
                if (RELU) { o.x = fmaxf(o.x, 0.0f); o.y = fmaxf(o.y, 0.0f); }
                *reinterpret_cast<float2*>(out + (size_t)r1 * DIM + col) = o;
            }
        }
    }
}

// ---------------- host orchestration ----------------
static const size_t GEMM_SMEM = 2u * 128u * SA * sizeof(float);  // 135168 B

static void run_layer(const float* hd_in, const float* hp_in,
                      float* hd_out, float* hp_out,
                      const float* Wt /*3x[n][k]*/, const float* b, bool relu,
                      const int* ddi_s, const int* ddi_d, int nE_ddi,
                      const int* pdi_s, const int* pdi_d, int nE_pdi,
                      const int* ppi_s, const int* ppi_d, int nE_ppi,
                      float* agg1, float* agg2, float* aggp, float* rs) {
    const size_t fbytes = (size_t)NDRUG * DIM * sizeof(float);
    cudaMemsetAsync(agg1, 0, fbytes, 0);
    cudaMemsetAsync(agg2, 0, fbytes, 0);
    cudaMemsetAsync(aggp, 0, (size_t)NPROT * DIM * sizeof(float), 0);

    scatter_kernel<<<(nE_ddi + 7) / 8, 256>>>(hd_in, ddi_s, ddi_d, rs + 0 * NDRUG, agg1, nE_ddi);
    scatter_kernel<<<(nE_pdi + 7) / 8, 256>>>(hp_in, pdi_s, pdi_d, rs + 2 * NDRUG, agg2, nE_pdi);
    scatter_kernel<<<(nE_ppi + 7) / 8, 256>>>(hp_in, ppi_s, ppi_d, rs + 4 * NDRUG, aggp, nE_ppi);

    const int gblocks = (NDRUG + 127) / 128;
    if (relu) {
        gemm_mma<true, true><<<gblocks, 256, GEMM_SMEM>>>(
            agg1, rs + 1 * NDRUG, agg2, rs + 3 * NDRUG,
            Wt + 0 * DIM * DIM, Wt + 1 * DIM * DIM, b + 0 * DIM, b + 1 * DIM, hd_out, NDRUG);
        gemm_mma<true, false><<<gblocks, 256, GEMM_SMEM>>>(
            aggp, rs + 5 * NDRUG, nullptr, nullptr,
            Wt + 2 * DIM * DIM, nullptr, b + 2 * DIM, nullptr, hp_out, NPROT);
    } else {
        gemm_mma<false, true><<<gblocks, 256, GEMM_SMEM>>>(
            agg1, rs + 1 * NDRUG, agg2, rs + 3 * NDRUG,
            Wt + 0 * DIM * DIM, Wt + 1 * DIM * DIM, b + 0 * DIM, b + 1 * DIM, hd_out, NDRUG);
        gemm_mma<false, false><<<gblocks, 256, GEMM_SMEM>>>(
            aggp, rs + 5 * NDRUG, nullptr, nullptr,
            Wt + 2 * DIM * DIM, nullptr, b + 2 * DIM, nullptr, hp_out, NPROT);
    }
}

extern "C" void kernel_launch(void* const* d_in, const int* in_sizes, int n_in,
                              void* d_out, int out_size) {
    const float* hd0   = (const float*)d_in[0];
    const float* hp0   = (const float*)d_in[1];
    const int*   ddi_s = (const int*)d_in[2];
    const int*   ddi_d = (const int*)d_in[3];
    const int*   pdi_s = (const int*)d_in[4];
    const int*   pdi_d = (const int*)d_in[5];
    const int*   ppi_s = (const int*)d_in[6];
    const int*   ppi_d = (const int*)d_in[7];
    const float* W1 = (const float*)d_in[8];
    const float* b1 = (const float*)d_in[9];
    const float* W2 = (const float*)d_in[10];
    const float* b2 = (const float*)d_in[11];
    const float* W3 = (const float*)d_in[12];
    const float* b3 = (const float*)d_in[13];

    const int nE_ddi = in_sizes[2];
    const int nE_pdi = in_sizes[4];
    const int nE_ppi = in_sizes[6];

    cudaFuncSetAttribute(gemm_mma<true, true>,   cudaFuncAttributeMaxDynamicSharedMemorySize, (int)GEMM_SMEM);
    cudaFuncSetAttribute(gemm_mma<true, false>,  cudaFuncAttributeMaxDynamicSharedMemorySize, (int)GEMM_SMEM);
    cudaFuncSetAttribute(gemm_mma<false, true>,  cudaFuncAttributeMaxDynamicSharedMemorySize, (int)GEMM_SMEM);
    cudaFuncSetAttribute(gemm_mma<false, false>, cudaFuncAttributeMaxDynamicSharedMemorySize, (int)GEMM_SMEM);

    float *hd1, *hp1, *hd2, *hp2, *agg1, *agg2, *aggp, *rs, *wt;
    cudaGetSymbolAddress((void**)&hd1, g_hd1);
    cudaGetSymbolAddress((void**)&hp1, g_hp1);
    cudaGetSymbolAddress((void**)&hd2, g_hd2);
    cudaGetSymbolAddress((void**)&hp2, g_hp2);
    cudaGetSymbolAddress((void**)&agg1, g_agg1);
    cudaGetSymbolAddress((void**)&agg2, g_agg2);
    cudaGetSymbolAddress((void**)&aggp, g_aggp);
    cudaGetSymbolAddress((void**)&rs, g_rs);
    cudaGetSymbolAddress((void**)&wt, g_Wt);

    // transposed+rounded weights: g_Wt[0..2]=W1, [3..5]=W2, [6..8]=W3
    {
        int n = 3 * DIM * DIM, blks = (n + 255) / 256;
        transpose_w<<<blks, 256>>>(W1, wt + 0 * 3 * DIM * DIM);
        transpose_w<<<blks, 256>>>(W2, wt + 1 * 3 * DIM * DIM);
        transpose_w<<<blks, 256>>>(W3, wt + 2 * 3 * DIM * DIM);
    }

    // degrees
    cudaMemsetAsync(rs, 0, (size_t)6 * NDRUG * sizeof(float), 0);
    {
        int cb = (nE_ddi + 255) / 256;
        count_kernel<<<cb, 256>>>(ddi_s, rs + 0 * NDRUG, nE_ddi);
        count_kernel<<<cb, 256>>>(ddi_d, rs + 1 * NDRUG, nE_ddi);
        cb = (nE_pdi + 255) / 256;
        count_kernel<<<cb, 256>>>(pdi_s, rs + 2 * NDRUG, nE_pdi);
        count_kernel<<<cb, 256>>>(pdi_d, rs + 3 * NDRUG, nE_pdi);
        cb = (nE_ppi + 255) / 256;
        count_kernel<<<cb, 256>>>(ppi_s, rs + 4 * NDRUG, nE_ppi);
        count_kernel<<<cb, 256>>>(ppi_d, rs + 5 * NDRUG, nE_ppi);
        rsqrt_kernel<<<(6 * NDRUG + 255) / 256, 256>>>(rs, 6 * NDRUG);
    }

    float* outd = (float*)d_out;
    float* outp = outd + (size_t)NDRUG * DIM;

    run_layer(hd0, hp0, hd1, hp1, wt + 0 * 3 * DIM * DIM, b1, true,
              ddi_s, ddi_d, nE_ddi, pdi_s, pdi_d, nE_pdi, ppi_s, ppi_d, nE_ppi,
              agg1, agg2, aggp, rs);
    run_layer(hd1, hp1, hd2, hp2, wt + 1 * 3 * DIM * DIM, b2, true,
              ddi_s, ddi_d, nE_ddi, pdi_s, pdi_d, nE_pdi, ppi_s, ppi_d, nE_ppi,
              agg1, agg2, aggp, rs);
    run_layer(hd2, hp2, outd, outp, wt + 2 * 3 * DIM * DIM, b3, false,
              ddi_s, ddi_d, nE_ddi, pdi_s, pdi_d, nE_pdi, ppi_s, ppi_d, nE_ppi,
              agg1, agg2, aggp, rs);
}

// round 4
// speedup vs baseline: 2.2914x; 1.6741x over previous
#include <cuda_runtime.h>
#include <cstdint>

#define NDRUG 100000
#define NPROT 100000
#define NN    100000            // nodes per type (drug == prot count)
#define NEMAX 800000
#define DIM   128
#define SA    132   // smem row stride in floats (conflict-free for quad patterns)

// ---------------- scratch (no runtime allocation allowed) ----------------
__device__ float g_hd1[(size_t)NDRUG * DIM];
__device__ float g_hp1[(size_t)NPROT * DIM];
__device__ float g_hd2[(size_t)NDRUG * DIM];
__device__ float g_hp2[(size_t)NPROT * DIM];
__device__ float g_agg1[(size_t)NDRUG * DIM];   // DDI aggregate (drug dst)
__device__ float g_agg2[(size_t)NDRUG * DIM];   // PDI aggregate (drug dst)
__device__ float g_aggp[(size_t)NPROT * DIM];   // PPI aggregate (protein dst)
// 6 rsqrt-degree arrays: [0]=ddi_out [1]=ddi_in [2]=pdi_out [3]=pdi_in [4]=ppi_out [5]=ppi_in
__device__ float g_rs[(size_t)6 * NN];
// transposed + tf32-rounded weights: 9 matrices of [n][k]
__device__ float g_Wt[(size_t)9 * DIM * DIM];
// CSR (by dst) per relation
__device__ int g_indptr[3 * (NN + 1)];
__device__ int g_cursor[3 * NN];
__device__ int g_eidx[3 * NEMAX];
__device__ int g_bsum[256];

// ---------------- degree kernels ----------------
__global__ void count_kernel(const int* __restrict__ idx, float* __restrict__ cnt, int n) {
    int i = blockIdx.x * blockDim.x + threadIdx.x;
    if (i < n) atomicAdd(&cnt[idx[i]], 1.0f);
}
__global__ void rsqrt_kernel(float* __restrict__ p, int n) {
    int i = blockIdx.x * blockDim.x + threadIdx.x;
    if (i < n) p[i] = rsqrtf(fmaxf(p[i], 1.0f));
}
// transpose 3 stacked [128x128] weight matrices to [n][k], rounding to tf32 once
__global__ void transpose_w(const float* __restrict__ W, float* __restrict__ Wt) {
    int i = blockIdx.x * blockDim.x + threadIdx.x;
    if (i < 3 * DIM * DIM) {
        int rel = i >> 14, rem = i & 16383;
        int k = rem >> 7, n = rem & 127;
        float v = W[i];
        uint32_t u;
        asm("cvt.rna.tf32.f32 %0, %1;" : "=r"(u) : "f"(v));
        Wt[(rel << 14) + (n << 7) + k] = __uint_as_float(u);
    }
}

// ---------------- exclusive scan (float counts -> int indptr) ----------------
__global__ void scan1(const float* __restrict__ cnt, int* __restrict__ excl,
                      int* __restrict__ bsum, int n) {
    __shared__ int sm2[1024];
    int tid = threadIdx.x;
    int i = blockIdx.x * 1024 + tid;
    int v = (i < n) ? (int)cnt[i] : 0;
    sm2[tid] = v;
    __syncthreads();
#pragma unroll
    for (int off = 1; off < 1024; off <<= 1) {
        int t2 = (tid >= off) ? sm2[tid - off] : 0;
        __syncthreads();
        sm2[tid] += t2;
        __syncthreads();
    }
    if (i < n) excl[i] = sm2[tid] - v;
    if (tid == 1023) bsum[blockIdx.x] = sm2[1023];
}
__global__ void scan2(int* __restrict__ bsum, int nb) {
    __shared__ int sm2[256];
    int tid = threadIdx.x;
    sm2[tid] = (tid < nb) ? bsum[tid] : 0;
    __syncthreads();
#pragma unroll
    for (int off = 1; off < 256; off <<= 1) {
        int t2 = (tid >= off) ? sm2[tid - off] : 0;
        __syncthreads();
        sm2[tid] += t2;
        __syncthreads();
    }
    if (tid < nb) bsum[tid] = sm2[tid];   // inclusive
}
__global__ void scan3(const float* __restrict__ cnt, int* __restrict__ excl,
                      const int* __restrict__ bsum, int n) {
    int i = blockIdx.x * blockDim.x + threadIdx.x;
    if (i < n) {
        int b = i >> 10;
        int off = b ? bsum[b - 1] : 0;
        int e = excl[i] + off;
        excl[i] = e;
        if (i == n - 1) excl[n] = e + (int)cnt[i];
    }
}
__global__ void fill_kernel(const int* __restrict__ src, const int* __restrict__ dst,
                            int* __restrict__ cursor, int* __restrict__ eidx, int nE) {
    int e = blockIdx.x * blockDim.x + threadIdx.x;
    if (e < nE) {
        int p = atomicAdd(&cursor[dst[e]], 1);
        eidx[p] = src[e];
    }
}

// ---------------- CSR gather: agg[d,:] = rs_in[d] * sum_e rs_out[src_e] * h[src_e,:] ----------------
__global__ void __launch_bounds__(256)
gather_kernel(const float* __restrict__ h, const int* __restrict__ indptr,
              const int* __restrict__ eidx, const float* __restrict__ rs_out,
              const float* __restrict__ rs_in, float* __restrict__ agg, int nrows) {
    int w = (blockIdx.x * blockDim.x + threadIdx.x) >> 5;
    int lane = threadIdx.x & 31;
    if (w >= nrows) return;
    int s0 = __ldg(indptr + w), s1 = __ldg(indptr + w + 1);
    float4 acc = make_float4(0.f, 0.f, 0.f, 0.f);
    for (int base = s0; base < s1; base += 32) {
        int m = min(32, s1 - base);
        int se = (lane < m) ? __ldg(eidx + base + lane) : 0;
        for (int i = 0; i < m; i++) {
            int s = __shfl_sync(0xFFFFFFFFu, se, i);
            float sc = __ldg(rs_out + s);
            float4 v = __ldg(reinterpret_cast<const float4*>(h + (size_t)s * DIM) + lane);
            acc.x += sc * v.x; acc.y += sc * v.y; acc.z += sc * v.z; acc.w += sc * v.w;
        }
    }
    float ri = __ldg(rs_in + w);
    acc.x *= ri; acc.y *= ri; acc.z *= ri; acc.w *= ri;
    reinterpret_cast<float4*>(agg + (size_t)w * DIM)[lane] = acc;
}

// ---------------- tf32 mma.sync GEMM ----------------
// out[m,:] = act( A1[m,:] @ W1 (+ A2[m,:] @ W2) + b1 (+ b2) )   (degree scaling pre-folded)
__device__ __forceinline__ void mma_tf32(float c[4], const uint32_t a[4], const uint32_t b[2]) {
    asm volatile(
        "mma.sync.aligned.m16n8k8.row.col.f32.tf32.tf32.f32 "
        "{%0,%1,%2,%3}, {%4,%5,%6,%7}, {%8,%9}, {%0,%1,%2,%3};"
        : "+f"(c[0]), "+f"(c[1]), "+f"(c[2]), "+f"(c[3])
        : "r"(a[0]), "r"(a[1]), "r"(a[2]), "r"(a[3]), "r"(b[0]), "r"(b[1]));
}

template<bool RELU, bool TWO>
__global__ void __launch_bounds__(256)
gemm_mma(const float* __restrict__ A1, const float* __restrict__ A2,
         const float* __restrict__ Wt1, const float* __restrict__ Wt2,
         const float* __restrict__ b1, const float* __restrict__ b2,
         float* __restrict__ out, int nrows) {
    extern __shared__ float sm[];
    float* As = sm;               // [128][SA]
    float* Ws = sm + 128 * SA;    // [128][SA]

    const int t = threadIdx.x;
    const int lane = t & 31, wid = t >> 5;
    const int wm = wid >> 2, wn = wid & 3;      // 2 x 4 warp grid
    const int row0 = blockIdx.x * 128;
    const int qid = lane >> 2, qtl = lane & 3;  // quad id / thread-in-quad

    float acc[4][4][4];
#pragma unroll
    for (int mi = 0; mi < 4; mi++)
#pragma unroll
        for (int ni = 0; ni < 4; ni++)
#pragma unroll
            for (int j = 0; j < 4; j++) acc[mi][ni][j] = 0.0f;

    const int nsrc = TWO ? 2 : 1;
    for (int s = 0; s < nsrc; s++) {
        const float* A  = s ? A2  : A1;
        const float* Wt = s ? Wt2 : Wt1;
        if (s) __syncthreads();   // prior mma reads done before smem overwrite

        // A tile: round to tf32, zero-pad past nrows
#pragma unroll
        for (int i = 0; i < 16; i++) {
            int e = t + 256 * i;
            int r = e >> 5, c4 = e & 31;
            int row = row0 + r;
            float4 v = make_float4(0.f, 0.f, 0.f, 0.f);
            if (row < nrows)
                v = __ldg(reinterpret_cast<const float4*>(A + (size_t)row * DIM) + c4);
            uint4 u;
            asm("cvt.rna.tf32.f32 %0, %1;" : "=r"(u.x) : "f"(v.x));
            asm("cvt.rna.tf32.f32 %0, %1;" : "=r"(u.y) : "f"(v.y));
            asm("cvt.rna.tf32.f32 %0, %1;" : "=r"(u.z) : "f"(v.z));
            asm("cvt.rna.tf32.f32 %0, %1;" : "=r"(u.w) : "f"(v.w));
            *reinterpret_cast<uint4*>(&As[r * SA + c4 * 4]) = u;
        }
        // W tile [n][k] (already tf32-rounded)
#pragma unroll
        for (int i = 0; i < 16; i++) {
            int e = t + 256 * i;
            int r = e >> 5, c4 = e & 31;
            float4 v = __ldg(reinterpret_cast<const float4*>(Wt + (size_t)r * DIM) + c4);
            *reinterpret_cast<float4*>(&Ws[r * SA + c4 * 4]) = v;
        }
        __syncthreads();

        // 16 k-steps of m16n8k8
#pragma unroll
        for (int ks = 0; ks < 16; ks++) {
            const int k0 = ks * 8;
            uint32_t a[4][4];
#pragma unroll
            for (int mi = 0; mi < 4; mi++) {
                const float* p = &As[(wm * 64 + mi * 16 + qid) * SA + k0 + qtl];
                a[mi][0] = __float_as_uint(p[0]);
                a[mi][1] = __float_as_uint(p[8 * SA]);
                a[mi][2] = __float_as_uint(p[4]);
                a[mi][3] = __float_as_uint(p[8 * SA + 4]);
            }
            uint32_t b[4][2];
#pragma unroll
            for (int ni = 0; ni < 4; ni++) {
                const float* p = &Ws[(wn * 32 + ni * 8 + qid) * SA + k0 + qtl];
                b[ni][0] = __float_as_uint(p[0]);
                b[ni][1] = __float_as_uint(p[4]);
            }
#pragma unroll
            for (int mi = 0; mi < 4; mi++)
#pragma unroll
                for (int ni = 0; ni < 4; ni++)
                    mma_tf32(acc[mi][ni], a[mi], b[ni]);
        }
    }

    // Epilogue: bias (+bias2), optional ReLU, float2 stores
#pragma unroll
    for (int ni = 0; ni < 4; ni++) {
        int col = wn * 32 + ni * 8 + qtl * 2;
        float bb0 = __ldg(b1 + col)     + (TWO ? __ldg(b2 + col)     : 0.0f);
        float bb1 = __ldg(b1 + col + 1) + (TWO ? __ldg(b2 + col + 1) : 0.0f);
#pragma unroll
        for (int mi = 0; mi < 4; mi++) {
            int r0 = row0 + wm * 64 + mi * 16 + qid;
            if (r0 < nrows) {
                float2 o;
                o.x = acc[mi][ni][0] + bb0;
                o.y = acc[mi][ni][1] + bb1;
                if (RELU) { o.x = fmaxf(o.x, 0.0f); o.y = fmaxf(o.y, 0.0f); }
                *reinterpret_cast<float2*>(out + (size_t)r0 * DIM + col) = o;
            }
            int r1 = r0 + 8;
            if (r1 < nrows) {
                float2 o;
                o.x = acc[mi][ni][2] + bb0;
                o.y = acc[mi][ni][3] + bb1;
                if (RELU) { o.x = fmaxf(o.x, 0.0f); o.y = fmaxf(o.y, 0.0f); }
                *reinterpret_cast<float2*>(out + (size_t)r1 * DIM + col) = o;
            }
        }
    }
}

// ---------------- host orchestration ----------------
static const size_t GEMM_SMEM = 2u * 128u * SA * sizeof(float);  // 135168 B

static void run_layer(const float* hd_in, const float* hp_in,
                      float* hd_out, float* hp_out,
                      const float* Wt /*3x[n][k]*/, const float* b, bool relu,
                      int* indptr, int* eidx,
                      float* agg1, float* agg2, float* aggp, float* rs) {
    const int gwb = (NN * 32 + 255) / 256;   // one warp per dst row
    gather_kernel<<<gwb, 256>>>(hd_in, indptr + 0 * (NN + 1), eidx + 0 * NEMAX,
                                rs + 0 * NN, rs + 1 * NN, agg1, NDRUG);
    gather_kernel<<<gwb, 256>>>(hp_in, indptr + 1 * (NN + 1), eidx + 1 * NEMAX,
                                rs + 2 * NN, rs + 3 * NN, agg2, NDRUG);
    gather_kernel<<<gwb, 256>>>(hp_in, indptr + 2 * (NN + 1), eidx + 2 * NEMAX,
                                rs + 4 * NN, rs + 5 * NN, aggp, NPROT);

    const int gblocks = (NDRUG + 127) / 128;
    if (relu) {
        gemm_mma<true, true><<<gblocks, 256, GEMM_SMEM>>>(
            agg1, agg2, Wt + 0 * DIM * DIM, Wt + 1 * DIM * DIM,
            b + 0 * DIM, b + 1 * DIM, hd_out, NDRUG);
        gemm_mma<true, false><<<gblocks, 256, GEMM_SMEM>>>(
            aggp, nullptr, Wt + 2 * DIM * DIM, nullptr,
            b + 2 * DIM, nullptr, hp_out, NPROT);
    } else {
        gemm_mma<false, true><<<gblocks, 256, GEMM_SMEM>>>(
            agg1, agg2, Wt + 0 * DIM * DIM, Wt + 1 * DIM * DIM,
            b + 0 * DIM, b + 1 * DIM, hd_out, NDRUG);
        gemm_mma<false, false><<<gblocks, 256, GEMM_SMEM>>>(
            aggp, nullptr, Wt + 2 * DIM * DIM, nullptr,
            b + 2 * DIM, nullptr, hp_out, NPROT);
    }
}

extern "C" void kernel_launch(void* const* d_in, const int* in_sizes, int n_in,
                              void* d_out, int out_size) {
    const float* hd0   = (const float*)d_in[0];
    const float* hp0   = (const float*)d_in[1];
    const int*   ddi_s = (const int*)d_in[2];
    const int*   ddi_d = (const int*)d_in[3];
    const int*   pdi_s = (const int*)d_in[4];
    const int*   pdi_d = (const int*)d_in[5];
    const int*   ppi_s = (const int*)d_in[6];
    const int*   ppi_d = (const int*)d_in[7];
    const float* W1 = (const float*)d_in[8];
    const float* b1 = (const float*)d_in[9];
    const float* W2 = (const float*)d_in[10];
    const float* b2 = (const float*)d_in[11];
    const float* W3 = (const float*)d_in[12];
    const float* b3 = (const float*)d_in[13];

    const int nE_ddi = in_sizes[2];
    const int nE_pdi = in_sizes[4];
    const int nE_ppi = in_sizes[6];

    cudaFuncSetAttribute(gemm_mma<true, true>,   cudaFuncAttributeMaxDynamicSharedMemorySize, (int)GEMM_SMEM);
    cudaFuncSetAttribute(gemm_mma<true, false>,  cudaFuncAttributeMaxDynamicSharedMemorySize, (int)GEMM_SMEM);
    cudaFuncSetAttribute(gemm_mma<false, true>,  cudaFuncAttributeMaxDynamicSharedMemorySize, (int)GEMM_SMEM);
    cudaFuncSetAttribute(gemm_mma<false, false>, cudaFuncAttributeMaxDynamicSharedMemorySize, (int)GEMM_SMEM);

    float *hd1, *hp1, *hd2, *hp2, *agg1, *agg2, *aggp, *rs, *wt;
    int *indptr, *cursor, *eidx, *bsum;
    cudaGetSymbolAddress((void**)&hd1, g_hd1);
    cudaGetSymbolAddress((void**)&hp1, g_hp1);
    cudaGetSymbolAddress((void**)&hd2, g_hd2);
    cudaGetSymbolAddress((void**)&hp2, g_hp2);
    cudaGetSymbolAddress((void**)&agg1, g_agg1);
    cudaGetSymbolAddress((void**)&agg2, g_agg2);
    cudaGetSymbolAddress((void**)&aggp, g_aggp);
    cudaGetSymbolAddress((void**)&rs, g_rs);
    cudaGetSymbolAddress((void**)&wt, g_Wt);
    cudaGetSymbolAddress((void**)&indptr, g_indptr);
    cudaGetSymbolAddress((void**)&cursor, g_cursor);
    cudaGetSymbolAddress((void**)&eidx, g_eidx);
    cudaGetSymbolAddress((void**)&bsum, g_bsum);

    // transposed+rounded weights
    {
        int n = 3 * DIM * DIM, blks = (n + 255) / 256;
        transpose_w<<<blks, 256>>>(W1, wt + 0 * 3 * DIM * DIM);
        transpose_w<<<blks, 256>>>(W2, wt + 1 * 3 * DIM * DIM);
        transpose_w<<<blks, 256>>>(W3, wt + 2 * 3 * DIM * DIM);
    }

    // degree histograms (float counts)
    cudaMemsetAsync(rs, 0, (size_t)6 * NN * sizeof(float), 0);
    {
        int cb = (nE_ddi + 255) / 256;
        count_kernel<<<cb, 256>>>(ddi_s, rs + 0 * NN, nE_ddi);
        count_kernel<<<cb, 256>>>(ddi_d, rs + 1 * NN, nE_ddi);
        cb = (nE_pdi + 255) / 256;
        count_kernel<<<cb, 256>>>(pdi_s, rs + 2 * NN, nE_pdi);
        count_kernel<<<cb, 256>>>(pdi_d, rs + 3 * NN, nE_pdi);
        cb = (nE_ppi + 255) / 256;
        count_kernel<<<cb, 256>>>(ppi_s, rs + 4 * NN, nE_ppi);
        count_kernel<<<cb, 256>>>(ppi_d, rs + 5 * NN, nE_ppi);
    }

    // CSR build per relation (from raw float in-degree counts, BEFORE rsqrt)
    const int nb = (NN + 1023) / 1024;
    const int tb = (NN + 255) / 256;
    // DDI (in-counts at rs+1*NN)
    scan1<<<nb, 1024>>>(rs + 1 * NN, indptr + 0 * (NN + 1), bsum, NN);
    scan2<<<1, 256>>>(bsum, nb);
    scan3<<<tb, 256>>>(rs + 1 * NN, indptr + 0 * (NN + 1), bsum, NN);
    // PDI
    scan1<<<nb, 1024>>>(rs + 3 * NN, indptr + 1 * (NN + 1), bsum, NN);
    scan2<<<1, 256>>>(bsum, nb);
    scan3<<<tb, 256>>>(rs + 3 * NN, indptr + 1 * (NN + 1), bsum, NN);
    // PPI
    scan1<<<nb, 1024>>>(rs + 5 * NN, indptr + 2 * (NN + 1), bsum, NN);
    scan2<<<1, 256>>>(bsum, nb);
    scan3<<<tb, 256>>>(rs + 5 * NN, indptr + 2 * (NN + 1), bsum, NN);

    cudaMemcpyAsync(cursor + 0 * NN, indptr + 0 * (NN + 1), NN * sizeof(int), cudaMemcpyDeviceToDevice, 0);
    cudaMemcpyAsync(cursor + 1 * NN, indptr + 1 * (NN + 1), NN * sizeof(int), cudaMemcpyDeviceToDevice, 0);
    cudaMemcpyAsync(cursor + 2 * NN, indptr + 2 * (NN + 1), NN * sizeof(int), cudaMemcpyDeviceToDevice, 0);

    fill_kernel<<<(nE_ddi + 255) / 256, 256>>>(ddi_s, ddi_d, cursor + 0 * NN, eidx + 0 * NEMAX, nE_ddi);
    fill_kernel<<<(nE_pdi + 255) / 256, 256>>>(pdi_s, pdi_d, cursor + 1 * NN, eidx + 1 * NEMAX, nE_pdi);
    fill_kernel<<<(nE_ppi + 255) / 256, 256>>>(ppi_s, ppi_d, cursor + 2 * NN, eidx + 2 * NEMAX, nE_ppi);

    // counts -> rsqrt(max(deg,1))  (after scans have consumed raw counts)
    rsqrt_kernel<<<(6 * NN + 255) / 256, 256>>>(rs, 6 * NN);

    float* outd = (float*)d_out;
    float* outp = outd + (size_t)NDRUG * DIM;

    run_layer(hd0, hp0, hd1, hp1, wt + 0 * 3 * DIM * DIM, b1, true,
              indptr, eidx, agg1, agg2, aggp, rs);
    run_layer(hd1, hp1, hd2, hp2, wt + 1 * 3 * DIM * DIM, b2, true,
              indptr, eidx, agg1, agg2, aggp, rs);
    run_layer(hd2, hp2, outd, outp, wt + 2 * 3 * DIM * DIM, b3, false,
              indptr, eidx, agg1, agg2, aggp, rs);
}